// round 5
// baseline (speedup 1.0000x reference)
#include <cuda_runtime.h>

// NARX RNN, D=4, HID=64, NX=16, NT=512, NGRID=2048, NY=1.
//
// R5 pipeline (3 launches):
//  1) u_kernel : U[tau][k][G] = relu(x[tau]·W_in + b_in)   (2 units/thread,
//                weight-broadcast amortized 2x; also zeroes out[t<D])
//  2) zw_kernel: Z[tau][j][G] = U·W_xh + b_h  AND  T[tau] = tanh(Z[tau])
//                (S=4 units/thread -> 4 fma2 per weight LDS)
//  3) narx_main: h = T[tau0] (coalesced load);  3x  h = tanh(Z + h·W_hh);
//                y = h·W_out + b_out.
// All data g-pair packed (f32x2); weights stored as u64 splat pairs in smem.

typedef unsigned long long u64;

#define NT   512
#define NG   2048
#define NGP  1024
#define NXF  16
#define DLY  4

__device__ u64 g_U[(size_t)NT * 64 * NGP];   // 268 MB  [tau][k][G]
__device__ u64 g_Z[(size_t)NT * 64 * NGP];   // 268 MB  [tau][j][G]
__device__ u64 g_T[(size_t)NT * 64 * NGP];   // 268 MB  [tau][j][G]

__device__ __forceinline__ u64 fma2(u64 a, u64 b, u64 c) {
    u64 d; asm("fma.rn.f32x2 %0, %1, %2, %3;" : "=l"(d) : "l"(a), "l"(b), "l"(c));
    return d;
}
__device__ __forceinline__ u64 add2(u64 a, u64 b) {
    u64 d; asm("add.rn.f32x2 %0, %1, %2;" : "=l"(d) : "l"(a), "l"(b));
    return d;
}
__device__ __forceinline__ u64 pack2(float x) {
    u64 r; asm("mov.b64 %0, {%1, %1};" : "=l"(r) : "f"(x));
    return r;
}
__device__ __forceinline__ u64 pack2b(float a, float b) {
    u64 r; asm("mov.b64 %0, {%1, %2};" : "=l"(r) : "f"(a), "f"(b));
    return r;
}
__device__ __forceinline__ void unpack2(u64 v, float& lo, float& hi) {
    asm("mov.b64 {%0, %1}, %2;" : "=f"(lo), "=f"(hi) : "l"(v));
}
__device__ __forceinline__ float tanh_fast(float v) {
    float e = __expf(2.0f * v);
    return 1.0f - __fdividef(2.0f, e + 1.0f);
}

// ---------------- kernel 1: U = relu(x·W_in + b_in), 2 units/thread --------
__global__ __launch_bounds__(128)
void u_kernel(const float* __restrict__ x,
              const float* __restrict__ W_in, const float* __restrict__ b_in,
              float* __restrict__ out)
{
    __shared__ u64 sW2[NXF * 64];   // 8 KB splat pairs
    __shared__ u64 sB2[64];
    const int tid = threadIdx.x;
    for (int i = tid; i < NXF * 64; i += 128) sW2[i] = pack2(W_in[i]);
    if (tid < 64) sB2[tid] = pack2(b_in[tid]);
    __syncthreads();

    const int b   = blockIdx.x;          // 512 * 4 blocks
    const int tau = b >> 2;
    const int G   = ((b & 3) << 7) + tid;   // unit A; unit B = G + 512

    // zero the t < D output rows (replaces the zero_head kernel)
    if (tau < DLY) {
        const float2 z0 = {0.0f, 0.0f};
        *(float2*)(out + (size_t)tau * NG + 2 * G)         = z0;
        *(float2*)(out + (size_t)tau * NG + 2 * (G + 512)) = z0;
    }

    u64 xa[16], xb[16];
    {
        const float4* xr = (const float4*)(x + ((size_t)tau * NG + 2 * G) * NXF);
        float4 r0[4] = { xr[0], xr[1], xr[2], xr[3] };
        float4 r1[4] = { xr[4], xr[5], xr[6], xr[7] };
        const float* fa = (const float*)r0;
        const float* fb = (const float*)r1;
        #pragma unroll
        for (int i = 0; i < 16; i++) xa[i] = pack2b(fa[i], fb[i]);
    }
    {
        const float4* xr = (const float4*)(x + ((size_t)tau * NG + 2 * (G + 512)) * NXF);
        float4 r0[4] = { xr[0], xr[1], xr[2], xr[3] };
        float4 r1[4] = { xr[4], xr[5], xr[6], xr[7] };
        const float* fa = (const float*)r0;
        const float* fb = (const float*)r1;
        #pragma unroll
        for (int i = 0; i < 16; i++) xb[i] = pack2b(fa[i], fb[i]);
    }

    u64* dst = g_U + (size_t)tau * 64 * NGP + G;
    #pragma unroll 4
    for (int k = 0; k < 64; k++) {
        u64 ua = sB2[k], ub = ua;
        #pragma unroll
        for (int i = 0; i < 16; i++) {
            const u64 w = sW2[i * 64 + k];
            ua = fma2(xa[i], w, ua);
            ub = fma2(xb[i], w, ub);
        }
        float a, c;
        unpack2(ua, a, c); ua = pack2b(fmaxf(a, 0.0f), fmaxf(c, 0.0f));
        unpack2(ub, a, c); ub = pack2b(fmaxf(a, 0.0f), fmaxf(c, 0.0f));
        dst[(size_t)k * NGP]       = ua;
        dst[(size_t)k * NGP + 512] = ub;
    }
}

// ---------------- kernel 2: Z = U·W_xh + b_h ; T = tanh(Z) -----------------
__global__ __launch_bounds__(128)
void zw_kernel(const float* __restrict__ W_xh, const float* __restrict__ b_h)
{
    __shared__ u64 sXh2[64 * 64];   // 32 KB splat pairs
    __shared__ u64 sBh2[64];
    const int tid = threadIdx.x;
    for (int i = tid; i < 64 * 64; i += 128) sXh2[i] = pack2(W_xh[i]);
    if (tid < 64) sBh2[tid] = pack2(b_h[tid]);
    __syncthreads();

    const int b   = blockIdx.x;          // 512 * 16 blocks
    const int tau = b >> 4;
    const int G0  = (b & 15) << 6;
    const int jt  = tid & 7;
    const int grp = tid >> 3;
    const int ub  = grp << 2;            // 4 units per thread

    u64 acc[4][8];
    #pragma unroll
    for (int jj = 0; jj < 8; jj++) {
        const u64 bb = sBh2[(jj << 3) + jt];
        acc[0][jj] = bb; acc[1][jj] = bb; acc[2][jj] = bb; acc[3][jj] = bb;
    }

    const u64* Up = g_U + (size_t)tau * 64 * NGP + (G0 + ub);
    const u64* wp = sXh2 + jt;
    #pragma unroll 1
    for (int k0 = 0; k0 < 64; k0 += 8) {
        #pragma unroll
        for (int kk = 0; kk < 8; kk++) {
            const ulonglong2 pa = *(const ulonglong2*)(Up + (size_t)kk * NGP);
            const ulonglong2 pb = *(const ulonglong2*)(Up + (size_t)kk * NGP + 2);
            const u64* w = wp + (kk << 6);
            #pragma unroll
            for (int jj = 0; jj < 8; jj++) {
                const u64 w2 = w[jj << 3];
                acc[0][jj] = fma2(pa.x, w2, acc[0][jj]);
                acc[1][jj] = fma2(pa.y, w2, acc[1][jj]);
                acc[2][jj] = fma2(pb.x, w2, acc[2][jj]);
                acc[3][jj] = fma2(pb.y, w2, acc[3][jj]);
            }
        }
        Up += 8 * NGP;
        wp += 8 * 64;
    }

    #pragma unroll
    for (int jj = 0; jj < 8; jj++) {
        const int j = (jj << 3) + jt;
        const size_t off = ((size_t)tau * 64 + j) * NGP + (G0 + ub);
        ulonglong2 za; za.x = acc[0][jj]; za.y = acc[1][jj];
        ulonglong2 zb; zb.x = acc[2][jj]; zb.y = acc[3][jj];
        *(ulonglong2*)(g_Z + off)     = za;
        *(ulonglong2*)(g_Z + off + 2) = zb;
        ulonglong2 ta, tb;
        float a, c;
        unpack2(za.x, a, c); ta.x = pack2b(tanh_fast(a), tanh_fast(c));
        unpack2(za.y, a, c); ta.y = pack2b(tanh_fast(a), tanh_fast(c));
        unpack2(zb.x, a, c); tb.x = pack2b(tanh_fast(a), tanh_fast(c));
        unpack2(zb.y, a, c); tb.y = pack2b(tanh_fast(a), tanh_fast(c));
        *(ulonglong2*)(g_T + off)     = ta;
        *(ulonglong2*)(g_T + off + 2) = tb;
    }
}

// ---------------- kernel 3: recurrence ------------------------------------
// smem: [0,34304) sH u64[64][67]; [34304,67072) sHh2 u64[64][64];
//       [67072,67584) sWo2 u64[64]; [67584,67588) sBo float
#define SMEM_BYTES 67592

__global__ __launch_bounds__(128, 3)
void narx_main(const float* __restrict__ W_hh, const float* __restrict__ W_out,
               const float* __restrict__ b_out, float* __restrict__ out)
{
    extern __shared__ char smem[];
    u64*   sH   = (u64*)smem;
    u64*   sHh2 = (u64*)(smem + 34304);
    u64*   sWo2 = (u64*)(smem + 67072);
    float* sBo  = (float*)(smem + 67584);

    const int tid = threadIdx.x;
    for (int i = tid; i < 4096; i += 128) sHh2[i] = pack2(W_hh[i]);
    if (tid < 64) sWo2[tid] = pack2(W_out[tid]);
    if (tid == 0) sBo[0] = b_out[0];

    const int b   = blockIdx.x;          // 508*16 blocks
    const int t   = DLY + (b >> 4);
    const int G0  = (b & 15) << 6;
    const int jt  = tid & 7;
    const int grp = tid >> 3;
    const int ub  = grp << 2;

    // ---- d = 0: cooperative, coalesced load of h = T[tau0] ----
    {
        const u64* Tp = g_T + (size_t)(t - DLY) * 64 * NGP + G0;
        #pragma unroll 4
        for (int idx = tid; idx < 4096; idx += 128) {
            const int j  = idx >> 6;
            const int Gi = idx & 63;
            sH[(size_t)Gi * 67 + j] = Tp[(size_t)j * NGP + Gi];
        }
    }
    __syncthreads();

    u64* hr0 = sH + (size_t)(ub + 0) * 67;
    u64* hr1 = sH + (size_t)(ub + 1) * 67;
    u64* hr2 = sH + (size_t)(ub + 2) * 67;
    u64* hr3 = sH + (size_t)(ub + 3) * 67;

    u64 acc[4][8];
    u64 y2[4] = {0ull, 0ull, 0ull, 0ull};

    // ---- d = 1..3: h = tanh(Z[tau] + h·W_hh) ----
    for (int d = 1; d < DLY; d++) {
        const int tau = t - DLY + d;

        #pragma unroll
        for (int jj = 0; jj < 8; jj++) {
            const int j = (jj << 3) + jt;
            const u64* zp = g_Z + ((size_t)tau * 64 + j) * NGP + (G0 + ub);
            const ulonglong2 za = *(const ulonglong2*)zp;
            const ulonglong2 zb = *(const ulonglong2*)(zp + 2);
            acc[0][jj] = za.x; acc[1][jj] = za.y;
            acc[2][jj] = zb.x; acc[3][jj] = zb.y;
        }

        const u64* wp = sHh2 + jt;
        #pragma unroll 1
        for (int k0 = 0; k0 < 64; k0 += 8) {
            #pragma unroll
            for (int kk = 0; kk < 8; kk++) {
                const int k = k0 + kk;
                const u64 h0 = hr0[k], h1 = hr1[k], h2 = hr2[k], h3 = hr3[k];
                const u64* w = wp + (k << 6);
                #pragma unroll
                for (int jj = 0; jj < 8; jj++) {
                    const u64 w2 = w[jj << 3];
                    acc[0][jj] = fma2(h0, w2, acc[0][jj]);
                    acc[1][jj] = fma2(h1, w2, acc[1][jj]);
                    acc[2][jj] = fma2(h2, w2, acc[2][jj]);
                    acc[3][jj] = fma2(h3, w2, acc[3][jj]);
                }
            }
        }

        __syncwarp();

        if (d < DLY - 1) {
            #pragma unroll
            for (int s = 0; s < 4; s++) {
                u64* hrs = sH + (size_t)(ub + s) * 67;
                #pragma unroll
                for (int jj = 0; jj < 8; jj++) {
                    float a, c; unpack2(acc[s][jj], a, c);
                    hrs[(jj << 3) + jt] = pack2b(tanh_fast(a), tanh_fast(c));
                }
            }
        } else {
            #pragma unroll
            for (int s = 0; s < 4; s++) {
                #pragma unroll
                for (int jj = 0; jj < 8; jj++) {
                    float a, c; unpack2(acc[s][jj], a, c);
                    const u64 hp = pack2b(tanh_fast(a), tanh_fast(c));
                    y2[s] = fma2(hp, sWo2[(jj << 3) + jt], y2[s]);
                }
            }
        }
        __syncwarp();
    }

    #pragma unroll
    for (int s = 0; s < 4; s++) {
        u64 v = y2[s];
        v = add2(v, __shfl_xor_sync(0xFFFFFFFFu, v, 1));
        v = add2(v, __shfl_xor_sync(0xFFFFFFFFu, v, 2));
        v = add2(v, __shfl_xor_sync(0xFFFFFFFFu, v, 4));
        y2[s] = v;
    }
    if (jt == 0) {
        const float bo = sBo[0];
        #pragma unroll
        for (int s = 0; s < 4; s++) {
            float a, c; unpack2(y2[s], a, c);
            float2 o; o.x = a + bo; o.y = c + bo;
            *(float2*)(out + (size_t)t * NG + 2 * (G0 + ub + s)) = o;
        }
    }
}

extern "C" void kernel_launch(void* const* d_in, const int* in_sizes, int n_in,
                              void* d_out, int out_size) {
    const float* x     = (const float*)d_in[0];
    const float* W_in  = (const float*)d_in[1];
    const float* b_in  = (const float*)d_in[2];
    const float* W_xh  = (const float*)d_in[3];
    const float* W_hh  = (const float*)d_in[4];
    const float* b_h   = (const float*)d_in[5];
    const float* W_out = (const float*)d_in[6];
    const float* b_out = (const float*)d_in[7];
    float* out = (float*)d_out;

    cudaFuncSetAttribute(narx_main, cudaFuncAttributeMaxDynamicSharedMemorySize,
                         SMEM_BYTES);

    u_kernel <<<NT * 4, 128>>>(x, W_in, b_in, out);
    zw_kernel<<<NT * 16, 128>>>(W_xh, b_h);
    narx_main<<<(NT - DLY) * 16, 128, SMEM_BYTES>>>(W_hh, W_out, b_out, out);
    (void)in_sizes; (void)n_in; (void)out_size;
}

// round 7
// speedup vs baseline: 1.1121x; 1.1121x over previous
#include <cuda_runtime.h>

// NARX RNN, D=4, HID=64, NX=16, NT=512, NGRID=2048, NY=1.
//
// R7 = R6 cleaned (infra retry):
//  1) uz_kernel : per (tau, G-chunk): U = relu(x·W_in+b_in) built in SMEM
//                 (never hits gmem), then Z = U·W_xh + b_h streamed to g_Z.
//                 Also zeroes out[t<D].
//  2) narx_main : h = tanh(Z[tau0]) loaded directly;
//                 3x  h = tanh(Z + h·W_hh);  y = h·W_out + b_out.
// Only g_Z scratch survives: ~0.84 GB total DRAM traffic (~2x less than R5).

typedef unsigned long long u64;

#define NT   512
#define NG   2048
#define NGP  1024
#define NXF  16
#define DLY  4

__device__ u64 g_Z[(size_t)NT * 64 * NGP];   // 268 MB  [tau][j][G]

__device__ __forceinline__ u64 fma2(u64 a, u64 b, u64 c) {
    u64 d; asm("fma.rn.f32x2 %0, %1, %2, %3;" : "=l"(d) : "l"(a), "l"(b), "l"(c));
    return d;
}
__device__ __forceinline__ u64 add2(u64 a, u64 b) {
    u64 d; asm("add.rn.f32x2 %0, %1, %2;" : "=l"(d) : "l"(a), "l"(b));
    return d;
}
__device__ __forceinline__ u64 pack2(float x) {
    u64 r; asm("mov.b64 %0, {%1, %1};" : "=l"(r) : "f"(x));
    return r;
}
__device__ __forceinline__ u64 pack2b(float a, float b) {
    u64 r; asm("mov.b64 %0, {%1, %2};" : "=l"(r) : "f"(a), "f"(b));
    return r;
}
__device__ __forceinline__ void unpack2(u64 v, float& lo, float& hi) {
    asm("mov.b64 {%0, %1}, %2;" : "=f"(lo), "=f"(hi) : "l"(v));
}
__device__ __forceinline__ float tanh_fast(float v) {
    float e = __expf(2.0f * v);
    return 1.0f - __fdividef(2.0f, e + 1.0f);
}

// ---------------- kernel 1: fused U (smem) -> Z (gmem) ---------------------
// Dynamic smem layout (bytes):
//   [0, 34816)       sU    : u64 [64 k][68]
//   [34816, 43008)   sWin2 : u64 [16*64] splat pairs
//   [43008, 75776)   sXh2  : u64 [64*64] splat pairs
//   [75776, 76288)   sBin2 : u64 [64]
//   [76288, 76800)   sBh2  : u64 [64]
#define UZ_SMEM 76800

__global__ __launch_bounds__(128, 2)
void uz_kernel(const float* __restrict__ x,
               const float* __restrict__ W_in, const float* __restrict__ b_in,
               const float* __restrict__ W_xh, const float* __restrict__ b_h,
               float* __restrict__ out)
{
    extern __shared__ char smem[];
    u64* sU    = (u64*)smem;
    u64* sWin2 = (u64*)(smem + 34816);
    u64* sXh2  = (u64*)(smem + 43008);
    u64* sBin2 = (u64*)(smem + 75776);
    u64* sBh2  = (u64*)(smem + 76288);

    const int tid = threadIdx.x;
    for (int i = tid; i < NXF * 64; i += 128) sWin2[i] = pack2(W_in[i]);
    for (int i = tid; i < 64 * 64;  i += 128) sXh2[i]  = pack2(W_xh[i]);
    if (tid < 64) { sBin2[tid] = pack2(b_in[tid]); sBh2[tid] = pack2(b_h[tid]); }

    const int b   = blockIdx.x;          // 512 * 16 blocks
    const int tau = b >> 4;
    const int G0  = (b & 15) << 6;       // 64 g-pair units per block

    // zero out[t < D] rows (the 16 blocks of each tau < D cover the row)
    if (tau < DLY && tid < 64) {
        const float2 z0 = {0.0f, 0.0f};
        *(float2*)(out + (size_t)tau * NG + 2 * (G0 + tid)) = z0;
    }

    // ---- phase A: U[k][unit] = relu(b_in[k] + x·W_in[:,k]) into smem ----
    {
        const int unit = tid & 63;
        const int kh   = tid >> 6;          // k-half: [32kh, 32kh+32)
        const int G    = G0 + unit;

        const float4* xr = (const float4*)(x + ((size_t)tau * NG + 2 * G) * NXF);
        float4 r0[4] = { xr[0], xr[1], xr[2], xr[3] };
        float4 r1[4] = { xr[4], xr[5], xr[6], xr[7] };
        const float* fa = (const float*)r0;
        const float* fb = (const float*)r1;
        u64 x2[16];
        #pragma unroll
        for (int i = 0; i < 16; i++) x2[i] = pack2b(fa[i], fb[i]);

        __syncthreads();   // weights staged before use

        #pragma unroll 4
        for (int kk = 0; kk < 32; kk++) {
            const int k = kh * 32 + kk;
            u64 u = sBin2[k];
            #pragma unroll
            for (int i = 0; i < 16; i++)
                u = fma2(x2[i], sWin2[i * 64 + k], u);
            float a, c; unpack2(u, a, c);
            sU[(size_t)k * 68 + unit] = pack2b(fmaxf(a, 0.0f), fmaxf(c, 0.0f));
        }
    }
    __syncthreads();   // U complete before phase B reads it

    // ---- phase B: Z[j][G] = b_h[j] + sum_k U[k][G] * W_xh[k][j] ----
    const int jt  = tid & 7;
    const int grp = tid >> 3;
    const int ub  = grp << 2;            // 4 units per thread

    u64 acc[4][8];
    #pragma unroll
    for (int jj = 0; jj < 8; jj++) {
        const u64 bb = sBh2[(jj << 3) + jt];
        acc[0][jj] = bb; acc[1][jj] = bb; acc[2][jj] = bb; acc[3][jj] = bb;
    }

    const u64* wp = sXh2 + jt;
    #pragma unroll 1
    for (int k0 = 0; k0 < 64; k0 += 8) {
        #pragma unroll
        for (int kk = 0; kk < 8; kk++) {
            const int k = k0 + kk;
            const ulonglong2 pa = *(const ulonglong2*)(sU + (size_t)k * 68 + ub);
            const ulonglong2 pb = *(const ulonglong2*)(sU + (size_t)k * 68 + ub + 2);
            const u64* w = wp + (k << 6);
            #pragma unroll
            for (int jj = 0; jj < 8; jj++) {
                const u64 w2 = w[jj << 3];
                acc[0][jj] = fma2(pa.x, w2, acc[0][jj]);
                acc[1][jj] = fma2(pa.y, w2, acc[1][jj]);
                acc[2][jj] = fma2(pb.x, w2, acc[2][jj]);
                acc[3][jj] = fma2(pb.y, w2, acc[3][jj]);
            }
        }
    }

    #pragma unroll
    for (int jj = 0; jj < 8; jj++) {
        const int j = (jj << 3) + jt;
        const size_t off = ((size_t)tau * 64 + j) * NGP + (G0 + ub);
        ulonglong2 za; za.x = acc[0][jj]; za.y = acc[1][jj];
        ulonglong2 zb; zb.x = acc[2][jj]; zb.y = acc[3][jj];
        *(ulonglong2*)(g_Z + off)     = za;
        *(ulonglong2*)(g_Z + off + 2) = zb;
    }
}

// ---------------- kernel 2: recurrence ------------------------------------
// smem: [0,34304) sH u64[64 units][67]; [34304,67072) sHh2 u64[64][64];
//       [67072,67584) sWo2 u64[64]; [67584,67588) sBo float
#define MAIN_SMEM 67592

__global__ __launch_bounds__(128, 3)
void narx_main(const float* __restrict__ W_hh, const float* __restrict__ W_out,
               const float* __restrict__ b_out, float* __restrict__ out)
{
    extern __shared__ char smem[];
    u64*   sH   = (u64*)smem;
    u64*   sHh2 = (u64*)(smem + 34304);
    u64*   sWo2 = (u64*)(smem + 67072);
    float* sBo  = (float*)(smem + 67584);

    const int tid = threadIdx.x;
    for (int i = tid; i < 4096; i += 128) sHh2[i] = pack2(W_hh[i]);
    if (tid < 64) sWo2[tid] = pack2(W_out[tid]);
    if (tid == 0) sBo[0] = b_out[0];
    __syncthreads();

    const int b   = blockIdx.x;          // 508*16 blocks
    const int t   = DLY + (b >> 4);
    const int G0  = (b & 15) << 6;
    const int jt  = tid & 7;
    const int grp = tid >> 3;
    const int ub  = grp << 2;

    u64* hr0 = sH + (size_t)(ub + 0) * 67;
    u64* hr1 = sH + (size_t)(ub + 1) * 67;
    u64* hr2 = sH + (size_t)(ub + 2) * 67;
    u64* hr3 = sH + (size_t)(ub + 3) * 67;

    // ---- d = 0: h = tanh(Z[tau0])  (group-local rows, warp-sync only) ----
    {
        const int tau = t - DLY;
        #pragma unroll
        for (int jj = 0; jj < 8; jj++) {
            const int j = (jj << 3) + jt;
            const u64* zp = g_Z + ((size_t)tau * 64 + j) * NGP + (G0 + ub);
            const ulonglong2 za = *(const ulonglong2*)zp;
            const ulonglong2 zb = *(const ulonglong2*)(zp + 2);
            float a, c;
            unpack2(za.x, a, c); hr0[j] = pack2b(tanh_fast(a), tanh_fast(c));
            unpack2(za.y, a, c); hr1[j] = pack2b(tanh_fast(a), tanh_fast(c));
            unpack2(zb.x, a, c); hr2[j] = pack2b(tanh_fast(a), tanh_fast(c));
            unpack2(zb.y, a, c); hr3[j] = pack2b(tanh_fast(a), tanh_fast(c));
        }
    }
    __syncwarp();

    u64 acc[4][8];
    u64 y2[4] = {0ull, 0ull, 0ull, 0ull};

    // ---- d = 1..3: h = tanh(Z[tau] + h·W_hh) ----
    for (int d = 1; d < DLY; d++) {
        const int tau = t - DLY + d;

        #pragma unroll
        for (int jj = 0; jj < 8; jj++) {
            const int j = (jj << 3) + jt;
            const u64* zp = g_Z + ((size_t)tau * 64 + j) * NGP + (G0 + ub);
            const ulonglong2 za = *(const ulonglong2*)zp;
            const ulonglong2 zb = *(const ulonglong2*)(zp + 2);
            acc[0][jj] = za.x; acc[1][jj] = za.y;
            acc[2][jj] = zb.x; acc[3][jj] = zb.y;
        }

        const u64* wp = sHh2 + jt;
        #pragma unroll 1
        for (int k0 = 0; k0 < 64; k0 += 8) {
            #pragma unroll
            for (int kk = 0; kk < 8; kk++) {
                const int k = k0 + kk;
                const u64 h0 = hr0[k], h1 = hr1[k], h2 = hr2[k], h3 = hr3[k];
                const u64* w = wp + (k << 6);
                #pragma unroll
                for (int jj = 0; jj < 8; jj++) {
                    const u64 w2 = w[jj << 3];
                    acc[0][jj] = fma2(h0, w2, acc[0][jj]);
                    acc[1][jj] = fma2(h1, w2, acc[1][jj]);
                    acc[2][jj] = fma2(h2, w2, acc[2][jj]);
                    acc[3][jj] = fma2(h3, w2, acc[3][jj]);
                }
            }
        }

        __syncwarp();

        if (d < DLY - 1) {
            #pragma unroll
            for (int s = 0; s < 4; s++) {
                u64* hrs = sH + (size_t)(ub + s) * 67;
                #pragma unroll
                for (int jj = 0; jj < 8; jj++) {
                    float a, c; unpack2(acc[s][jj], a, c);
                    hrs[(jj << 3) + jt] = pack2b(tanh_fast(a), tanh_fast(c));
                }
            }
        } else {
            #pragma unroll
            for (int s = 0; s < 4; s++) {
                #pragma unroll
                for (int jj = 0; jj < 8; jj++) {
                    float a, c; unpack2(acc[s][jj], a, c);
                    const u64 hp = pack2b(tanh_fast(a), tanh_fast(c));
                    y2[s] = fma2(hp, sWo2[(jj << 3) + jt], y2[s]);
                }
            }
        }
        __syncwarp();
    }

    #pragma unroll
    for (int s = 0; s < 4; s++) {
        u64 v = y2[s];
        v = add2(v, __shfl_xor_sync(0xFFFFFFFFu, v, 1));
        v = add2(v, __shfl_xor_sync(0xFFFFFFFFu, v, 2));
        v = add2(v, __shfl_xor_sync(0xFFFFFFFFu, v, 4));
        y2[s] = v;
    }
    if (jt == 0) {
        const float bo = sBo[0];
        #pragma unroll
        for (int s = 0; s < 4; s++) {
            float a, c; unpack2(y2[s], a, c);
            float2 o; o.x = a + bo; o.y = c + bo;
            *(float2*)(out + (size_t)t * NG + 2 * (G0 + ub + s)) = o;
        }
    }
}

extern "C" void kernel_launch(void* const* d_in, const int* in_sizes, int n_in,
                              void* d_out, int out_size) {
    const float* x     = (const float*)d_in[0];
    const float* W_in  = (const float*)d_in[1];
    const float* b_in  = (const float*)d_in[2];
    const float* W_xh  = (const float*)d_in[3];
    const float* W_hh  = (const float*)d_in[4];
    const float* b_h   = (const float*)d_in[5];
    const float* W_out = (const float*)d_in[6];
    const float* b_out = (const float*)d_in[7];
    float* out = (float*)d_out;

    cudaFuncSetAttribute(uz_kernel, cudaFuncAttributeMaxDynamicSharedMemorySize,
                         UZ_SMEM);
    cudaFuncSetAttribute(narx_main, cudaFuncAttributeMaxDynamicSharedMemorySize,
                         MAIN_SMEM);

    uz_kernel<<<NT * 16, 128, UZ_SMEM>>>(x, W_in, b_in, W_xh, b_h, out);
    narx_main<<<(NT - DLY) * 16, 128, MAIN_SMEM>>>(W_hh, W_out, b_out, out);
    (void)in_sizes; (void)n_in; (void)out_size;
}

// round 8
// speedup vs baseline: 1.1347x; 1.0203x over previous
#include <cuda_runtime.h>

// NARX RNN, D=4, HID=64, NX=16, NT=512, NGRID=2048, NY=1.
//
// R8 = R7 with crossbar-byte reduction in both hot inner loops:
//  - weight splat tables reordered so each thread reads 2 splat weights per
//    LDS.128 (8 lanes' chunks = one contiguous 128B span, conflict-free).
//  - h / U tiles stored k-major so 4 units' values come from 2 LDS.128
//    (group windows on disjoint bank quartets).
// Per warp per step: 1536 -> ~768 crossbar cycles; kernel becomes fma-bound.

typedef unsigned long long u64;

#define NT   512
#define NG   2048
#define NGP  1024
#define NXF  16
#define DLY  4

__device__ u64 g_Z[(size_t)NT * 64 * NGP];   // 268 MB  [tau][j][G]

__device__ __forceinline__ u64 fma2(u64 a, u64 b, u64 c) {
    u64 d; asm("fma.rn.f32x2 %0, %1, %2, %3;" : "=l"(d) : "l"(a), "l"(b), "l"(c));
    return d;
}
__device__ __forceinline__ u64 add2(u64 a, u64 b) {
    u64 d; asm("add.rn.f32x2 %0, %1, %2;" : "=l"(d) : "l"(a), "l"(b));
    return d;
}
__device__ __forceinline__ u64 pack2(float x) {
    u64 r; asm("mov.b64 %0, {%1, %1};" : "=l"(r) : "f"(x));
    return r;
}
__device__ __forceinline__ u64 pack2b(float a, float b) {
    u64 r; asm("mov.b64 %0, {%1, %2};" : "=l"(r) : "f"(a), "f"(b));
    return r;
}
__device__ __forceinline__ void unpack2(u64 v, float& lo, float& hi) {
    asm("mov.b64 {%0, %1}, %2;" : "=f"(lo), "=f"(hi) : "l"(v));
}
__device__ __forceinline__ float tanh_fast(float v) {
    float e = __expf(2.0f * v);
    return 1.0f - __fdividef(2.0f, e + 1.0f);
}

// Reordered splat-weight slot for (k, j):  j = 8*jj + jt,  jj = 2m + b
//   slot = k*64 + m*16 + jt*2 + b
// Thread jt reads ulonglong2 at k*64 + m*16 + jt*2 -> splats for jj=2m, 2m+1.
__device__ __forceinline__ int wslot(int k, int j) {
    const int jt = j & 7, jj = j >> 3;
    return k * 64 + (jj >> 1) * 16 + jt * 2 + (jj & 1);
}

#define HPAD 66   // k-major tile row length in u64 (528 B, 16B-aligned rows)

// ---------------- kernel 1: fused U (smem) -> Z (gmem) ---------------------
// Dynamic smem layout (bytes):
//   [0, 33792)       sU    : u64 [64 k][HPAD]   (k-major)
//   [33792, 41984)   sWin2 : u64 [16*64] splat pairs (plain layout)
//   [41984, 74752)   sXh2  : u64 [64*64] splat pairs (REORDERED layout)
//   [74752, 75264)   sBin2 : u64 [64]
//   [75264, 75776)   sBh2  : u64 [64]
#define UZ_SMEM 75776

__global__ __launch_bounds__(128, 2)
void uz_kernel(const float* __restrict__ x,
               const float* __restrict__ W_in, const float* __restrict__ b_in,
               const float* __restrict__ W_xh, const float* __restrict__ b_h,
               float* __restrict__ out)
{
    extern __shared__ char smem[];
    u64* sU    = (u64*)smem;
    u64* sWin2 = (u64*)(smem + 33792);
    u64* sXh2  = (u64*)(smem + 41984);
    u64* sBin2 = (u64*)(smem + 74752);
    u64* sBh2  = (u64*)(smem + 75264);

    const int tid = threadIdx.x;
    for (int i = tid; i < NXF * 64; i += 128) sWin2[i] = pack2(W_in[i]);
    for (int i = tid; i < 64 * 64;  i += 128)
        sXh2[wslot(i >> 6, i & 63)] = pack2(W_xh[i]);
    if (tid < 64) { sBin2[tid] = pack2(b_in[tid]); sBh2[tid] = pack2(b_h[tid]); }

    const int b   = blockIdx.x;          // 512 * 16 blocks
    const int tau = b >> 4;
    const int G0  = (b & 15) << 6;       // 64 g-pair units per block

    if (tau < DLY && tid < 64) {
        const float2 z0 = {0.0f, 0.0f};
        *(float2*)(out + (size_t)tau * NG + 2 * (G0 + tid)) = z0;
    }

    // ---- phase A: U[k][unit] = relu(b_in[k] + x·W_in[:,k]), k-major ----
    {
        const int unit = tid & 63;
        const int kh   = tid >> 6;          // k-half: [32kh, 32kh+32)
        const int G    = G0 + unit;

        const float4* xr = (const float4*)(x + ((size_t)tau * NG + 2 * G) * NXF);
        float4 r0[4] = { xr[0], xr[1], xr[2], xr[3] };
        float4 r1[4] = { xr[4], xr[5], xr[6], xr[7] };
        const float* fa = (const float*)r0;
        const float* fb = (const float*)r1;
        u64 x2[16];
        #pragma unroll
        for (int i = 0; i < 16; i++) x2[i] = pack2b(fa[i], fb[i]);

        __syncthreads();   // weights staged

        #pragma unroll 4
        for (int kk = 0; kk < 32; kk++) {
            const int k = kh * 32 + kk;
            u64 u = sBin2[k];
            #pragma unroll
            for (int i = 0; i < 16; i++)
                u = fma2(x2[i], sWin2[i * 64 + k], u);
            float a, c; unpack2(u, a, c);
            sU[(size_t)k * HPAD + unit] = pack2b(fmaxf(a, 0.0f), fmaxf(c, 0.0f));
        }
    }
    __syncthreads();   // U complete

    // ---- phase B: Z[j][G] = b_h[j] + sum_k U[k][G] * W_xh[k][j] ----
    const int jt  = tid & 7;
    const int grp = tid >> 3;
    const int ub  = grp << 2;            // 4 units per thread

    u64 acc[4][8];
    #pragma unroll
    for (int jj = 0; jj < 8; jj++) {
        const u64 bb = sBh2[(jj << 3) + jt];
        acc[0][jj] = bb; acc[1][jj] = bb; acc[2][jj] = bb; acc[3][jj] = bb;
    }

    #pragma unroll 1
    for (int k0 = 0; k0 < 64; k0 += 8) {
        #pragma unroll
        for (int kk = 0; kk < 8; kk++) {
            const int k = k0 + kk;
            const ulonglong2 ua = *(const ulonglong2*)(sU + (size_t)k * HPAD + ub);
            const ulonglong2 ubv = *(const ulonglong2*)(sU + (size_t)k * HPAD + ub + 2);
            const u64* wb = sXh2 + k * 64 + jt * 2;
            #pragma unroll
            for (int m = 0; m < 4; m++) {
                const ulonglong2 wm = *(const ulonglong2*)(wb + m * 16);
                acc[0][2*m]   = fma2(ua.x,  wm.x, acc[0][2*m]);
                acc[1][2*m]   = fma2(ua.y,  wm.x, acc[1][2*m]);
                acc[2][2*m]   = fma2(ubv.x, wm.x, acc[2][2*m]);
                acc[3][2*m]   = fma2(ubv.y, wm.x, acc[3][2*m]);
                acc[0][2*m+1] = fma2(ua.x,  wm.y, acc[0][2*m+1]);
                acc[1][2*m+1] = fma2(ua.y,  wm.y, acc[1][2*m+1]);
                acc[2][2*m+1] = fma2(ubv.x, wm.y, acc[2][2*m+1]);
                acc[3][2*m+1] = fma2(ubv.y, wm.y, acc[3][2*m+1]);
            }
        }
    }

    #pragma unroll
    for (int jj = 0; jj < 8; jj++) {
        const int j = (jj << 3) + jt;
        const size_t off = ((size_t)tau * 64 + j) * NGP + (G0 + ub);
        ulonglong2 za; za.x = acc[0][jj]; za.y = acc[1][jj];
        ulonglong2 zb; zb.x = acc[2][jj]; zb.y = acc[3][jj];
        *(ulonglong2*)(g_Z + off)     = za;
        *(ulonglong2*)(g_Z + off + 2) = zb;
    }
}

// ---------------- kernel 2: recurrence ------------------------------------
// smem: [0, 33792)  sH   u64[64 k][HPAD]  (k-major: sH[k][unit])
//       [33792, 66560) sHh2 u64[64*64] splat pairs (REORDERED)
//       [66560, 67072) sWo2 u64[64]
//       [67072, 67076) sBo float
#define MAIN_SMEM 67080

__global__ __launch_bounds__(128, 3)
void narx_main(const float* __restrict__ W_hh, const float* __restrict__ W_out,
               const float* __restrict__ b_out, float* __restrict__ out)
{
    extern __shared__ char smem[];
    u64*   sH   = (u64*)smem;
    u64*   sHh2 = (u64*)(smem + 33792);
    u64*   sWo2 = (u64*)(smem + 66560);
    float* sBo  = (float*)(smem + 67072);

    const int tid = threadIdx.x;
    for (int i = tid; i < 4096; i += 128)
        sHh2[wslot(i >> 6, i & 63)] = pack2(W_hh[i]);
    if (tid < 64) sWo2[tid] = pack2(W_out[tid]);
    if (tid == 0) sBo[0] = b_out[0];
    __syncthreads();

    const int b   = blockIdx.x;          // 508*16 blocks
    const int t   = DLY + (b >> 4);
    const int G0  = (b & 15) << 6;
    const int jt  = tid & 7;
    const int grp = tid >> 3;
    const int ub  = grp << 2;

    // ---- d = 0: h = tanh(Z[tau0]), written k-major (group-local units) ----
    {
        const int tau = t - DLY;
        #pragma unroll
        for (int jj = 0; jj < 8; jj++) {
            const int j = (jj << 3) + jt;
            const u64* zp = g_Z + ((size_t)tau * 64 + j) * NGP + (G0 + ub);
            const ulonglong2 za = *(const ulonglong2*)zp;
            const ulonglong2 zb = *(const ulonglong2*)(zp + 2);
            u64* hj = sH + (size_t)j * HPAD + ub;
            float a, c;
            unpack2(za.x, a, c); hj[0] = pack2b(tanh_fast(a), tanh_fast(c));
            unpack2(za.y, a, c); hj[1] = pack2b(tanh_fast(a), tanh_fast(c));
            unpack2(zb.x, a, c); hj[2] = pack2b(tanh_fast(a), tanh_fast(c));
            unpack2(zb.y, a, c); hj[3] = pack2b(tanh_fast(a), tanh_fast(c));
        }
    }
    __syncwarp();

    u64 acc[4][8];
    u64 y2[4] = {0ull, 0ull, 0ull, 0ull};

    // ---- d = 1..3: h = tanh(Z[tau] + h·W_hh) ----
    for (int d = 1; d < DLY; d++) {
        const int tau = t - DLY + d;

        #pragma unroll
        for (int jj = 0; jj < 8; jj++) {
            const int j = (jj << 3) + jt;
            const u64* zp = g_Z + ((size_t)tau * 64 + j) * NGP + (G0 + ub);
            const ulonglong2 za = *(const ulonglong2*)zp;
            const ulonglong2 zb = *(const ulonglong2*)(zp + 2);
            acc[0][jj] = za.x; acc[1][jj] = za.y;
            acc[2][jj] = zb.x; acc[3][jj] = zb.y;
        }

        #pragma unroll 1
        for (int k0 = 0; k0 < 64; k0 += 8) {
            #pragma unroll
            for (int kk = 0; kk < 8; kk++) {
                const int k = k0 + kk;
                const ulonglong2 ha = *(const ulonglong2*)(sH + (size_t)k * HPAD + ub);
                const ulonglong2 hb = *(const ulonglong2*)(sH + (size_t)k * HPAD + ub + 2);
                const u64* wb = sHh2 + k * 64 + jt * 2;
                #pragma unroll
                for (int m = 0; m < 4; m++) {
                    const ulonglong2 wm = *(const ulonglong2*)(wb + m * 16);
                    acc[0][2*m]   = fma2(ha.x, wm.x, acc[0][2*m]);
                    acc[1][2*m]   = fma2(ha.y, wm.x, acc[1][2*m]);
                    acc[2][2*m]   = fma2(hb.x, wm.x, acc[2][2*m]);
                    acc[3][2*m]   = fma2(hb.y, wm.x, acc[3][2*m]);
                    acc[0][2*m+1] = fma2(ha.x, wm.y, acc[0][2*m+1]);
                    acc[1][2*m+1] = fma2(ha.y, wm.y, acc[1][2*m+1]);
                    acc[2][2*m+1] = fma2(hb.x, wm.y, acc[2][2*m+1]);
                    acc[3][2*m+1] = fma2(hb.y, wm.y, acc[3][2*m+1]);
                }
            }
        }

        __syncwarp();   // done reading old h before overwriting

        if (d < DLY - 1) {
            #pragma unroll
            for (int jj = 0; jj < 8; jj++) {
                const int j = (jj << 3) + jt;
                u64* hj = sH + (size_t)j * HPAD + ub;
                float a, c;
                unpack2(acc[0][jj], a, c); hj[0] = pack2b(tanh_fast(a), tanh_fast(c));
                unpack2(acc[1][jj], a, c); hj[1] = pack2b(tanh_fast(a), tanh_fast(c));
                unpack2(acc[2][jj], a, c); hj[2] = pack2b(tanh_fast(a), tanh_fast(c));
                unpack2(acc[3][jj], a, c); hj[3] = pack2b(tanh_fast(a), tanh_fast(c));
            }
        } else {
            #pragma unroll
            for (int s = 0; s < 4; s++) {
                #pragma unroll
                for (int jj = 0; jj < 8; jj++) {
                    float a, c; unpack2(acc[s][jj], a, c);
                    const u64 hp = pack2b(tanh_fast(a), tanh_fast(c));
                    y2[s] = fma2(hp, sWo2[(jj << 3) + jt], y2[s]);
                }
            }
        }
        __syncwarp();
    }

    #pragma unroll
    for (int s = 0; s < 4; s++) {
        u64 v = y2[s];
        v = add2(v, __shfl_xor_sync(0xFFFFFFFFu, v, 1));
        v = add2(v, __shfl_xor_sync(0xFFFFFFFFu, v, 2));
        v = add2(v, __shfl_xor_sync(0xFFFFFFFFu, v, 4));
        y2[s] = v;
    }
    if (jt == 0) {
        const float bo = sBo[0];
        #pragma unroll
        for (int s = 0; s < 4; s++) {
            float a, c; unpack2(y2[s], a, c);
            float2 o; o.x = a + bo; o.y = c + bo;
            *(float2*)(out + (size_t)t * NG + 2 * (G0 + ub + s)) = o;
        }
    }
}

extern "C" void kernel_launch(void* const* d_in, const int* in_sizes, int n_in,
                              void* d_out, int out_size) {
    const float* x     = (const float*)d_in[0];
    const float* W_in  = (const float*)d_in[1];
    const float* b_in  = (const float*)d_in[2];
    const float* W_xh  = (const float*)d_in[3];
    const float* W_hh  = (const float*)d_in[4];
    const float* b_h   = (const float*)d_in[5];
    const float* W_out = (const float*)d_in[6];
    const float* b_out = (const float*)d_in[7];
    float* out = (float*)d_out;

    cudaFuncSetAttribute(uz_kernel, cudaFuncAttributeMaxDynamicSharedMemorySize,
                         UZ_SMEM);
    cudaFuncSetAttribute(narx_main, cudaFuncAttributeMaxDynamicSharedMemorySize,
                         MAIN_SMEM);

    uz_kernel<<<NT * 16, 128, UZ_SMEM>>>(x, W_in, b_in, W_xh, b_h, out);
    narx_main<<<(NT - DLY) * 16, 128, MAIN_SMEM>>>(W_hh, W_out, b_out, out);
    (void)in_sizes; (void)n_in; (void)out_size;
}

// round 10
// speedup vs baseline: 1.8727x; 1.6505x over previous
#include <cuda_runtime.h>
#include <cuda_bf16.h>
#include <cstdint>

// NARX RNN, D=4, HID=64, NX=16, NT=512, NGRID=2048, NY=1.
//
// R10: tensor-core recurrence via family-portable mma.sync (tcgen05 is not
// available under the harness's sm_103-family compile target).
//  1) uz_kernel (R8 SIMT): Z[tau][j][g] = relu(x·W_in+b_in)·W_xh + b_h
//  2) narx_tc: per CTA = 128 sequences x 64 hid.  Per step
//     D = [h_hi|h_hi|h_lo](128x192) x [W_hi|W_lo|W_hi](192x64) via
//     mma.sync.m16n8k16 bf16 (register accumulators, split precision),
//     h' = tanh(D + Z) -> bf16 hi/lo into padded SMEM -> ldmatrix next step.
//     Each warp owns its 32 rows: warp-synchronous recurrence.

typedef unsigned long long u64;

#define NT   512
#define NG   2048
#define NGP  1024
#define NXF  16
#define DLY  4

__device__ u64 g_Z[(size_t)NT * 64 * NGP];   // 268 MB; float view: [tau][j][g]

// ---------------- f32x2 helpers (uz kernel) ----------------
__device__ __forceinline__ u64 fma2(u64 a, u64 b, u64 c) {
    u64 d; asm("fma.rn.f32x2 %0, %1, %2, %3;" : "=l"(d) : "l"(a), "l"(b), "l"(c));
    return d;
}
__device__ __forceinline__ u64 pack2(float x) {
    u64 r; asm("mov.b64 %0, {%1, %1};" : "=l"(r) : "f"(x));
    return r;
}
__device__ __forceinline__ u64 pack2b(float a, float b) {
    u64 r; asm("mov.b64 %0, {%1, %2};" : "=l"(r) : "f"(a), "f"(b));
    return r;
}
__device__ __forceinline__ void unpack2(u64 v, float& lo, float& hi) {
    asm("mov.b64 {%0, %1}, %2;" : "=f"(lo), "=f"(hi) : "l"(v));
}
__device__ __forceinline__ float tanh_fast(float v) {
    float e = __expf(2.0f * v);
    return 1.0f - __fdividef(2.0f, e + 1.0f);
}

// ---------------- mma.sync / ldmatrix wrappers ----------------
__device__ __forceinline__ uint32_t s2u(const void* p) {
    uint32_t a;
    asm("{ .reg .u64 t; cvta.to.shared.u64 t, %1; cvt.u32.u64 %0, t; }" : "=r"(a) : "l"(p));
    return a;
}
__device__ __forceinline__ void ldsm_x4(uint32_t& r0, uint32_t& r1,
                                        uint32_t& r2, uint32_t& r3, uint32_t a) {
    asm volatile("ldmatrix.sync.aligned.m8n8.x4.shared.b16 {%0,%1,%2,%3}, [%4];"
                 : "=r"(r0), "=r"(r1), "=r"(r2), "=r"(r3) : "r"(a));
}
__device__ __forceinline__ void ldsm_x2(uint32_t& r0, uint32_t& r1, uint32_t a) {
    asm volatile("ldmatrix.sync.aligned.m8n8.x2.shared.b16 {%0,%1}, [%2];"
                 : "=r"(r0), "=r"(r1) : "r"(a));
}
__device__ __forceinline__ void mma_bf16(float* d, const uint32_t* a,
                                         uint32_t b0, uint32_t b1) {
    asm volatile("mma.sync.aligned.m16n8k16.row.col.f32.bf16.bf16.f32 "
                 "{%0,%1,%2,%3}, {%4,%5,%6,%7}, {%8,%9}, {%0,%1,%2,%3};"
                 : "+f"(d[0]), "+f"(d[1]), "+f"(d[2]), "+f"(d[3])
                 : "r"(a[0]), "r"(a[1]), "r"(a[2]), "r"(a[3]), "r"(b0), "r"(b1));
}
// pack (lo_elem=e, hi_elem=o) -> bf16x2  (first PTX src = HIGH half)
__device__ __forceinline__ uint32_t bfpack(float e, float o) {
    uint32_t r;
    asm("cvt.rn.bf16x2.f32 %0, %1, %2;" : "=r"(r) : "f"(o), "f"(e));
    return r;
}

// ---------------- kernel 1: fused U (smem) -> Z (gmem) [R8, unchanged] -----
__device__ __forceinline__ int wslot(int k, int j) {
    const int jt = j & 7, jj = j >> 3;
    return k * 64 + (jj >> 1) * 16 + jt * 2 + (jj & 1);
}
#define HPAD 66
#define UZ_SMEM 75776

__global__ __launch_bounds__(128, 2)
void uz_kernel(const float* __restrict__ x,
               const float* __restrict__ W_in, const float* __restrict__ b_in,
               const float* __restrict__ W_xh, const float* __restrict__ b_h,
               float* __restrict__ out)
{
    extern __shared__ char smem[];
    u64* sU    = (u64*)smem;
    u64* sWin2 = (u64*)(smem + 33792);
    u64* sXh2  = (u64*)(smem + 41984);
    u64* sBin2 = (u64*)(smem + 74752);
    u64* sBh2  = (u64*)(smem + 75264);

    const int tid = threadIdx.x;
    for (int i = tid; i < NXF * 64; i += 128) sWin2[i] = pack2(W_in[i]);
    for (int i = tid; i < 64 * 64;  i += 128)
        sXh2[wslot(i >> 6, i & 63)] = pack2(W_xh[i]);
    if (tid < 64) { sBin2[tid] = pack2(b_in[tid]); sBh2[tid] = pack2(b_h[tid]); }

    const int b   = blockIdx.x;
    const int tau = b >> 4;
    const int G0  = (b & 15) << 6;

    if (tau < DLY && tid < 64) {
        const float2 z0 = {0.0f, 0.0f};
        *(float2*)(out + (size_t)tau * NG + 2 * (G0 + tid)) = z0;
    }

    {
        const int unit = tid & 63;
        const int kh   = tid >> 6;
        const int G    = G0 + unit;

        const float4* xr = (const float4*)(x + ((size_t)tau * NG + 2 * G) * NXF);
        float4 r0[4] = { xr[0], xr[1], xr[2], xr[3] };
        float4 r1[4] = { xr[4], xr[5], xr[6], xr[7] };
        const float* fa = (const float*)r0;
        const float* fb = (const float*)r1;
        u64 x2[16];
        #pragma unroll
        for (int i = 0; i < 16; i++) x2[i] = pack2b(fa[i], fb[i]);

        __syncthreads();

        #pragma unroll 4
        for (int kk = 0; kk < 32; kk++) {
            const int k = kh * 32 + kk;
            u64 u = sBin2[k];
            #pragma unroll
            for (int i = 0; i < 16; i++)
                u = fma2(x2[i], sWin2[i * 64 + k], u);
            float a, c; unpack2(u, a, c);
            sU[(size_t)k * HPAD + unit] = pack2b(fmaxf(a, 0.0f), fmaxf(c, 0.0f));
        }
    }
    __syncthreads();

    const int jt  = tid & 7;
    const int grp = tid >> 3;
    const int ub  = grp << 2;

    u64 acc[4][8];
    #pragma unroll
    for (int jj = 0; jj < 8; jj++) {
        const u64 bb = sBh2[(jj << 3) + jt];
        acc[0][jj] = bb; acc[1][jj] = bb; acc[2][jj] = bb; acc[3][jj] = bb;
    }

    #pragma unroll 1
    for (int k0 = 0; k0 < 64; k0 += 8) {
        #pragma unroll
        for (int kk = 0; kk < 8; kk++) {
            const int k = k0 + kk;
            const ulonglong2 ua  = *(const ulonglong2*)(sU + (size_t)k * HPAD + ub);
            const ulonglong2 ubv = *(const ulonglong2*)(sU + (size_t)k * HPAD + ub + 2);
            const u64* wb = sXh2 + k * 64 + jt * 2;
            #pragma unroll
            for (int m = 0; m < 4; m++) {
                const ulonglong2 wm = *(const ulonglong2*)(wb + m * 16);
                acc[0][2*m]   = fma2(ua.x,  wm.x, acc[0][2*m]);
                acc[1][2*m]   = fma2(ua.y,  wm.x, acc[1][2*m]);
                acc[2][2*m]   = fma2(ubv.x, wm.x, acc[2][2*m]);
                acc[3][2*m]   = fma2(ubv.y, wm.x, acc[3][2*m]);
                acc[0][2*m+1] = fma2(ua.x,  wm.y, acc[0][2*m+1]);
                acc[1][2*m+1] = fma2(ua.y,  wm.y, acc[1][2*m+1]);
                acc[2][2*m+1] = fma2(ubv.x, wm.y, acc[2][2*m+1]);
                acc[3][2*m+1] = fma2(ubv.y, wm.y, acc[3][2*m+1]);
            }
        }
    }

    #pragma unroll
    for (int jj = 0; jj < 8; jj++) {
        const int j = (jj << 3) + jt;
        const size_t off = ((size_t)tau * 64 + j) * NGP + (G0 + ub);
        ulonglong2 za; za.x = acc[0][jj]; za.y = acc[1][jj];
        ulonglong2 zb; zb.x = acc[2][jj]; zb.y = acc[3][jj];
        *(ulonglong2*)(g_Z + off)     = za;
        *(ulonglong2*)(g_Z + off + 2) = zb;
    }
}

// ---------------- kernel 2: mma.sync recurrence ----------------------------
// H rows padded to 72 bf16 (144 B): ldmatrix bank-index r mod 8 -> conflict-free.
// B rows padded to 136 bf16 (272 B), layout [n][k]: k 0..63 = W_hi, 64..127 = W_lo.
#define HP 72
#define BP 136
#define OFF_HLO 18432              // Hhi: 128*72*2 = 18432
#define OFF_B   36864              // Hlo: another 18432
#define OFF_WO  54272              // B: 64*136*2 = 17408
#define OFF_BO  54528
#define TC_SMEM 54784

__global__ __launch_bounds__(128)
void narx_tc(const float* __restrict__ W_hh, const float* __restrict__ W_out,
             const float* __restrict__ b_out, float* __restrict__ out)
{
    extern __shared__ char sm[];
    const uint32_t sbase = s2u(sm);
    __nv_bfloat16* Bm  = (__nv_bfloat16*)(sm + OFF_B);
    float* sWo = (float*)(sm + OFF_WO);
    float* sBo = (float*)(sm + OFF_BO);

    const int tid  = threadIdx.x;
    const int lane = tid & 31;
    const int wrp  = tid >> 5;

    // stage B = [W_hi | W_lo] per n-row (seg2 of the MMA reuses the hi tiles)
    for (int idx = tid; idx < 4096; idx += 128) {
        const int k = idx >> 6, j = idx & 63;
        const float w = W_hh[idx];
        const __nv_bfloat16 hb = __float2bfloat16(w);
        const __nv_bfloat16 lb = __float2bfloat16(w - __bfloat162float(hb));
        Bm[j * BP + k]      = hb;
        Bm[j * BP + 64 + k] = lb;
    }
    if (tid < 64) sWo[tid] = W_out[tid];
    if (tid == 0) sBo[0] = b_out[0];
    __syncthreads();

    const int b  = blockIdx.x;                 // 508*16
    const int t  = DLY + (b >> 4);
    const int g0 = (b & 15) << 7;              // 128 sequences per CTA
    const float* Zf = (const float*)g_Z;

    // per-lane ldmatrix address components
    const int aRow = (lane & 7) + ((lane >> 3) & 1) * 8;   // within 16-row tile
    const int aCol = (lane >> 4) << 3;                     // 0 or 8 (k-half)
    const int bRow = lane & 7;
    const int bCol = ((lane >> 3) & 1) * 8;
    const int m0w  = wrp << 5;                 // warp's first row
    const uint32_t aHi0 = sbase +             ((m0w + aRow) * HP + aCol) * 2;
    const uint32_t aLo0 = sbase + OFF_HLO +   ((m0w + aRow) * HP + aCol) * 2;
    const uint32_t bB0  = sbase + OFF_B   +   (bRow * BP + bCol) * 2;

    const int qr = lane >> 2;                  // D-frag row within tile
    const int qc = (lane & 3) << 1;            // D-frag col pair base

    float dacc[2][8][4];
    float yacc[2][2] = {{0.f, 0.f}, {0.f, 0.f}};

    for (int d = 0; d < 4; d++) {
        const int tau = t - DLY + d;

        if (d == 0) {
            #pragma unroll
            for (int mt = 0; mt < 2; mt++)
                #pragma unroll
                for (int n = 0; n < 8; n++)
                    #pragma unroll
                    for (int q = 0; q < 4; q++) dacc[mt][n][q] = 0.0f;
        } else {
            #pragma unroll
            for (int mt = 0; mt < 2; mt++)
                #pragma unroll
                for (int n = 0; n < 8; n++)
                    #pragma unroll
                    for (int q = 0; q < 4; q++) dacc[mt][n][q] = 0.0f;
            #pragma unroll
            for (int kt = 0; kt < 4; kt++) {
                uint32_t ahi[2][4], alo[2][4];
                #pragma unroll
                for (int mt = 0; mt < 2; mt++) {
                    const uint32_t moff = (mt * 16 * HP + kt * 16) * 2;
                    ldsm_x4(ahi[mt][0], ahi[mt][1], ahi[mt][2], ahi[mt][3], aHi0 + moff);
                    ldsm_x4(alo[mt][0], alo[mt][1], alo[mt][2], alo[mt][3], aLo0 + moff);
                }
                #pragma unroll
                for (int n = 0; n < 8; n++) {
                    uint32_t bh0, bh1, bl0, bl1;
                    ldsm_x2(bh0, bh1, bB0 + (n * 8 * BP + kt * 16) * 2);
                    ldsm_x2(bl0, bl1, bB0 + (n * 8 * BP + 64 + kt * 16) * 2);
                    #pragma unroll
                    for (int mt = 0; mt < 2; mt++) {
                        mma_bf16(dacc[mt][n], ahi[mt], bh0, bh1);  // hi*Whi
                        mma_bf16(dacc[mt][n], ahi[mt], bl0, bl1);  // hi*Wlo
                        mma_bf16(dacc[mt][n], alo[mt], bh0, bh1);  // lo*Whi
                    }
                }
            }
        }

        __syncwarp();   // all ldmatrix reads of H done before rewriting it

        #pragma unroll
        for (int mt = 0; mt < 2; mt++) {
            const int r0 = m0w + mt * 16 + qr;
            #pragma unroll
            for (int n = 0; n < 8; n++) {
                const int c0 = (n << 3) + qc;
                const size_t zb = (((size_t)tau << 6) + c0) << 11;
                const float z00 = Zf[zb + g0 + r0];
                const float z01 = Zf[zb + 2048 + g0 + r0];
                const float z10 = Zf[zb + g0 + r0 + 8];
                const float z11 = Zf[zb + 2048 + g0 + r0 + 8];

                const float h00 = tanh_fast(dacc[mt][n][0] + z00);
                const float h01 = tanh_fast(dacc[mt][n][1] + z01);
                const float h10 = tanh_fast(dacc[mt][n][2] + z10);
                const float h11 = tanh_fast(dacc[mt][n][3] + z11);

                if (d < 3) {
                    const uint32_t p0 = bfpack(h00, h01);   // row r0
                    const uint32_t p1 = bfpack(h10, h11);   // row r0+8
                    const float f00 = __uint_as_float(p0 << 16);
                    const float f01 = __uint_as_float(p0 & 0xFFFF0000u);
                    const float f10 = __uint_as_float(p1 << 16);
                    const float f11 = __uint_as_float(p1 & 0xFFFF0000u);
                    const uint32_t q0 = bfpack(h00 - f00, h01 - f01);
                    const uint32_t q1 = bfpack(h10 - f10, h11 - f11);
                    const int o0 = (r0 * HP + c0) * 2;
                    const int o1 = ((r0 + 8) * HP + c0) * 2;
                    *(uint32_t*)(sm + o0)            = p0;
                    *(uint32_t*)(sm + o1)            = p1;
                    *(uint32_t*)(sm + OFF_HLO + o0)  = q0;
                    *(uint32_t*)(sm + OFF_HLO + o1)  = q1;
                } else {
                    const float w0 = sWo[c0], w1 = sWo[c0 + 1];
                    yacc[mt][0] += h00 * w0 + h01 * w1;
                    yacc[mt][1] += h10 * w0 + h11 * w1;
                }
            }
        }
        __syncwarp();   // new h visible before next step's ldmatrix
    }

    // reduce y over the 4-lane quad owning each row, write 4 outputs
    const float bo = sBo[0];
    #pragma unroll
    for (int mt = 0; mt < 2; mt++)
        #pragma unroll
        for (int hf = 0; hf < 2; hf++) {
            float v = yacc[mt][hf];
            v += __shfl_xor_sync(0xFFFFFFFFu, v, 1);
            v += __shfl_xor_sync(0xFFFFFFFFu, v, 2);
            if ((lane & 3) == 0) {
                const int row = m0w + mt * 16 + qr + hf * 8;
                out[(size_t)t * NG + g0 + row] = v + bo;
            }
        }
}

extern "C" void kernel_launch(void* const* d_in, const int* in_sizes, int n_in,
                              void* d_out, int out_size) {
    const float* x     = (const float*)d_in[0];
    const float* W_in  = (const float*)d_in[1];
    const float* b_in  = (const float*)d_in[2];
    const float* W_xh  = (const float*)d_in[3];
    const float* W_hh  = (const float*)d_in[4];
    const float* b_h   = (const float*)d_in[5];
    const float* W_out = (const float*)d_in[6];
    const float* b_out = (const float*)d_in[7];
    float* out = (float*)d_out;

    cudaFuncSetAttribute(uz_kernel, cudaFuncAttributeMaxDynamicSharedMemorySize,
                         UZ_SMEM);
    cudaFuncSetAttribute(narx_tc, cudaFuncAttributeMaxDynamicSharedMemorySize,
                         TC_SMEM);

    uz_kernel<<<NT * 16, 128, UZ_SMEM>>>(x, W_in, b_in, W_xh, b_h, out);
    narx_tc<<<(NT - DLY) * 16, 128, TC_SMEM>>>(W_hh, W_out, b_out, out);
    (void)in_sizes; (void)n_in; (void)out_size;
}

// round 11
// speedup vs baseline: 1.9778x; 1.0561x over previous
#include <cuda_runtime.h>
#include <cuda_bf16.h>
#include <cstdint>

// NARX RNN, D=4, HID=64, NX=16, NT=512, NGRID=2048, NY=1.
//
// R11: tensor cores in BOTH kernels (family-portable mma.sync bf16 split).
//  1) uz_tc  : phase A (SIMT f32x2): U = relu(x·W_in+b_in) -> bf16 hi/lo smem;
//              phase B (mma): Z = [U_hi|U_hi|U_lo]x[Wxh_hi|Wxh_lo|Wxh_hi] + b_h
//              scattered to g_Z[tau][j][g].
//  2) narx_tc: unchanged R10 recurrence (mma split, h in padded smem,
//              warp-synchronous 3-step loop, folded W_out epilogue).

typedef unsigned long long u64;

#define NT   512
#define NG   2048
#define NGP  1024
#define NXF  16
#define DLY  4

__device__ u64 g_Z[(size_t)NT * 64 * NGP];   // 268 MB; float view: [tau][j][g]

// ---------------- f32x2 helpers ----------------
__device__ __forceinline__ u64 fma2(u64 a, u64 b, u64 c) {
    u64 d; asm("fma.rn.f32x2 %0, %1, %2, %3;" : "=l"(d) : "l"(a), "l"(b), "l"(c));
    return d;
}
__device__ __forceinline__ u64 pack2(float x) {
    u64 r; asm("mov.b64 %0, {%1, %1};" : "=l"(r) : "f"(x));
    return r;
}
__device__ __forceinline__ u64 pack2b(float a, float b) {
    u64 r; asm("mov.b64 %0, {%1, %2};" : "=l"(r) : "f"(a), "f"(b));
    return r;
}
__device__ __forceinline__ void unpack2(u64 v, float& lo, float& hi) {
    asm("mov.b64 {%0, %1}, %2;" : "=f"(lo), "=f"(hi) : "l"(v));
}
__device__ __forceinline__ float tanh_fast(float v) {
    float e = __expf(2.0f * v);
    return 1.0f - __fdividef(2.0f, e + 1.0f);
}

// ---------------- mma.sync / ldmatrix wrappers ----------------
__device__ __forceinline__ uint32_t s2u(const void* p) {
    uint32_t a;
    asm("{ .reg .u64 t; cvta.to.shared.u64 t, %1; cvt.u32.u64 %0, t; }" : "=r"(a) : "l"(p));
    return a;
}
__device__ __forceinline__ void ldsm_x4(uint32_t& r0, uint32_t& r1,
                                        uint32_t& r2, uint32_t& r3, uint32_t a) {
    asm volatile("ldmatrix.sync.aligned.m8n8.x4.shared.b16 {%0,%1,%2,%3}, [%4];"
                 : "=r"(r0), "=r"(r1), "=r"(r2), "=r"(r3) : "r"(a));
}
__device__ __forceinline__ void ldsm_x2(uint32_t& r0, uint32_t& r1, uint32_t a) {
    asm volatile("ldmatrix.sync.aligned.m8n8.x2.shared.b16 {%0,%1}, [%2];"
                 : "=r"(r0), "=r"(r1) : "r"(a));
}
__device__ __forceinline__ void mma_bf16(float* d, const uint32_t* a,
                                         uint32_t b0, uint32_t b1) {
    asm volatile("mma.sync.aligned.m16n8k16.row.col.f32.bf16.bf16.f32 "
                 "{%0,%1,%2,%3}, {%4,%5,%6,%7}, {%8,%9}, {%0,%1,%2,%3};"
                 : "+f"(d[0]), "+f"(d[1]), "+f"(d[2]), "+f"(d[3])
                 : "r"(a[0]), "r"(a[1]), "r"(a[2]), "r"(a[3]), "r"(b0), "r"(b1));
}
// pack (elem0=e -> low half, elem1=o -> high half)
__device__ __forceinline__ uint32_t bfpack(float e, float o) {
    uint32_t r;
    asm("cvt.rn.bf16x2.f32 %0, %1, %2;" : "=r"(r) : "f"(o), "f"(e));
    return r;
}

#define HP 72     // padded row length (bf16) for ldmatrix-fed tiles
#define BP 136    // padded B row (bf16): [hi(64) | lo(64) | pad]

// ================= kernel 1: uz_tc =================
// smem: [0,18432) Uhi bf16[128][HP]; [18432,36864) Ulo;
//       [36864,54272) B bf16[64][BP] (W_xh hi|lo);
//       [54272,54528) sBh float[64];
//       [54528,62720) sWin2 u64[16*64] splat; [62720,63232) sBin2 u64[64]
#define UZ_OFF_ULO 18432
#define UZ_OFF_B   36864
#define UZ_OFF_BH  54272
#define UZ_OFF_WIN 54528
#define UZ_OFF_BIN 62720
#define UZ_SMEM    63232

__global__ __launch_bounds__(128)
void uz_tc(const float* __restrict__ x,
           const float* __restrict__ W_in, const float* __restrict__ b_in,
           const float* __restrict__ W_xh, const float* __restrict__ b_h,
           float* __restrict__ out)
{
    extern __shared__ char sm[];
    const uint32_t sbase = s2u(sm);
    __nv_bfloat16* Bm  = (__nv_bfloat16*)(sm + UZ_OFF_B);
    float* sBh   = (float*)(sm + UZ_OFF_BH);
    u64*   sWin2 = (u64*)(sm + UZ_OFF_WIN);
    u64*   sBin2 = (u64*)(sm + UZ_OFF_BIN);

    const int tid  = threadIdx.x;
    const int lane = tid & 31;
    const int wrp  = tid >> 5;

    for (int i = tid; i < NXF * 64; i += 128) sWin2[i] = pack2(W_in[i]);
    for (int idx = tid; idx < 4096; idx += 128) {
        const int k = idx >> 6, j = idx & 63;
        const float w = W_xh[idx];
        const __nv_bfloat16 hb = __float2bfloat16(w);
        const __nv_bfloat16 lb = __float2bfloat16(w - __bfloat162float(hb));
        Bm[j * BP + k]      = hb;
        Bm[j * BP + 64 + k] = lb;
    }
    if (tid < 64) { sBin2[tid] = pack2(b_in[tid]); sBh[tid] = b_h[tid]; }

    const int b   = blockIdx.x;          // 512 * 16
    const int tau = b >> 4;
    const int g0  = (b & 15) << 7;       // 128 g per CTA

    if (tau < DLY && tid < 64) {
        const float2 z0 = {0.0f, 0.0f};
        *(float2*)(out + (size_t)tau * NG + g0 + 2 * tid) = z0;
    }

    // ---- phase A: U = relu(x·W_in + b_in), bf16 hi/lo into smem ----
    {
        const int unit = tid >> 1;          // g-pair 0..63  (rows 2u, 2u+1)
        const int kh   = tid & 1;           // k-half [32kh, 32kh+32)
        const int re   = 2 * unit, ro = re + 1;

        const float4* xr = (const float4*)(x + ((size_t)tau * NG + g0 + re) * NXF);
        float4 r0[4] = { xr[0], xr[1], xr[2], xr[3] };   // row even
        float4 r1[4] = { xr[4], xr[5], xr[6], xr[7] };   // row odd
        const float* fa = (const float*)r0;
        const float* fb = (const float*)r1;
        u64 x2[16];
        #pragma unroll
        for (int i = 0; i < 16; i++) x2[i] = pack2b(fa[i], fb[i]);

        __syncthreads();   // staging done before smem reads/writes

        __nv_bfloat16* Uhi = (__nv_bfloat16*)sm;
        __nv_bfloat16* Ulo = (__nv_bfloat16*)(sm + UZ_OFF_ULO);

        #pragma unroll 4
        for (int kk = 0; kk < 16; kk++) {
            const int k = kh * 32 + 2 * kk;
            u64 u0 = sBin2[k], u1 = sBin2[k + 1];
            #pragma unroll
            for (int i = 0; i < 16; i++) {
                u0 = fma2(x2[i], sWin2[i * 64 + k],     u0);
                u1 = fma2(x2[i], sWin2[i * 64 + k + 1], u1);
            }
            float e0, o0, e1, o1;
            unpack2(u0, e0, o0); unpack2(u1, e1, o1);
            e0 = fmaxf(e0, 0.0f); o0 = fmaxf(o0, 0.0f);
            e1 = fmaxf(e1, 0.0f); o1 = fmaxf(o1, 0.0f);

            // even row: elems (k,k+1) = (e0,e1); odd row: (o0,o1)
            const uint32_t pE = bfpack(e0, e1);
            const uint32_t pO = bfpack(o0, o1);
            const float fE0 = __uint_as_float(pE << 16);
            const float fE1 = __uint_as_float(pE & 0xFFFF0000u);
            const float fO0 = __uint_as_float(pO << 16);
            const float fO1 = __uint_as_float(pO & 0xFFFF0000u);
            const uint32_t qE = bfpack(e0 - fE0, e1 - fE1);
            const uint32_t qO = bfpack(o0 - fO0, o1 - fO1);

            *(uint32_t*)(Uhi + re * HP + k) = pE;
            *(uint32_t*)(Uhi + ro * HP + k) = pO;
            *(uint32_t*)(Ulo + re * HP + k) = qE;
            *(uint32_t*)(Ulo + ro * HP + k) = qO;
        }
    }
    __syncthreads();

    // ---- phase B: Z = [Uhi|Uhi|Ulo] x [Whi|Wlo|Whi] + b_h -> g_Z ----
    const int aRow = (lane & 7) + ((lane >> 3) & 1) * 8;
    const int aCol = (lane >> 4) << 3;
    const int bRow = lane & 7;
    const int bCol = ((lane >> 3) & 1) * 8;
    const int m0w  = wrp << 5;
    const uint32_t aHi0 = sbase +              ((m0w + aRow) * HP + aCol) * 2;
    const uint32_t aLo0 = sbase + UZ_OFF_ULO + ((m0w + aRow) * HP + aCol) * 2;
    const uint32_t bB0  = sbase + UZ_OFF_B   + (bRow * BP + bCol) * 2;

    const int qr = lane >> 2;
    const int qc = (lane & 3) << 1;

    float dacc[2][8][4];
    #pragma unroll
    for (int mt = 0; mt < 2; mt++)
        #pragma unroll
        for (int n = 0; n < 8; n++)
            #pragma unroll
            for (int q = 0; q < 4; q++) dacc[mt][n][q] = 0.0f;

    #pragma unroll
    for (int kt = 0; kt < 4; kt++) {
        uint32_t ahi[2][4], alo[2][4];
        #pragma unroll
        for (int mt = 0; mt < 2; mt++) {
            const uint32_t moff = (mt * 16 * HP + kt * 16) * 2;
            ldsm_x4(ahi[mt][0], ahi[mt][1], ahi[mt][2], ahi[mt][3], aHi0 + moff);
            ldsm_x4(alo[mt][0], alo[mt][1], alo[mt][2], alo[mt][3], aLo0 + moff);
        }
        #pragma unroll
        for (int n = 0; n < 8; n++) {
            uint32_t bh0, bh1, bl0, bl1;
            ldsm_x2(bh0, bh1, bB0 + (n * 8 * BP + kt * 16) * 2);
            ldsm_x2(bl0, bl1, bB0 + (n * 8 * BP + 64 + kt * 16) * 2);
            #pragma unroll
            for (int mt = 0; mt < 2; mt++) {
                mma_bf16(dacc[mt][n], ahi[mt], bh0, bh1);
                mma_bf16(dacc[mt][n], ahi[mt], bl0, bl1);
                mma_bf16(dacc[mt][n], alo[mt], bh0, bh1);
            }
        }
    }

    float* Zf = (float*)g_Z;
    #pragma unroll
    for (int mt = 0; mt < 2; mt++) {
        const int r0 = m0w + mt * 16 + qr;
        #pragma unroll
        for (int n = 0; n < 8; n++) {
            const int c0 = (n << 3) + qc;
            const float b0 = sBh[c0], b1 = sBh[c0 + 1];
            const size_t zb = (((size_t)tau << 6) + c0) << 11;
            Zf[zb + g0 + r0]               = dacc[mt][n][0] + b0;
            Zf[zb + 2048 + g0 + r0]        = dacc[mt][n][1] + b1;
            Zf[zb + g0 + r0 + 8]           = dacc[mt][n][2] + b0;
            Zf[zb + 2048 + g0 + r0 + 8]    = dacc[mt][n][3] + b1;
        }
    }
}

// ================= kernel 2: narx_tc (unchanged R10) =================
#define OFF_HLO 18432
#define OFF_B   36864
#define OFF_WO  54272
#define OFF_BO  54528
#define TC_SMEM 54784

__global__ __launch_bounds__(128)
void narx_tc(const float* __restrict__ W_hh, const float* __restrict__ W_out,
             const float* __restrict__ b_out, float* __restrict__ out)
{
    extern __shared__ char sm[];
    const uint32_t sbase = s2u(sm);
    __nv_bfloat16* Bm  = (__nv_bfloat16*)(sm + OFF_B);
    float* sWo = (float*)(sm + OFF_WO);
    float* sBo = (float*)(sm + OFF_BO);

    const int tid  = threadIdx.x;
    const int lane = tid & 31;
    const int wrp  = tid >> 5;

    for (int idx = tid; idx < 4096; idx += 128) {
        const int k = idx >> 6, j = idx & 63;
        const float w = W_hh[idx];
        const __nv_bfloat16 hb = __float2bfloat16(w);
        const __nv_bfloat16 lb = __float2bfloat16(w - __bfloat162float(hb));
        Bm[j * BP + k]      = hb;
        Bm[j * BP + 64 + k] = lb;
    }
    if (tid < 64) sWo[tid] = W_out[tid];
    if (tid == 0) sBo[0] = b_out[0];
    __syncthreads();

    const int b  = blockIdx.x;                 // 508*16
    const int t  = DLY + (b >> 4);
    const int g0 = (b & 15) << 7;
    const float* Zf = (const float*)g_Z;

    const int aRow = (lane & 7) + ((lane >> 3) & 1) * 8;
    const int aCol = (lane >> 4) << 3;
    const int bRow = lane & 7;
    const int bCol = ((lane >> 3) & 1) * 8;
    const int m0w  = wrp << 5;
    const uint32_t aHi0 = sbase +           ((m0w + aRow) * HP + aCol) * 2;
    const uint32_t aLo0 = sbase + OFF_HLO + ((m0w + aRow) * HP + aCol) * 2;
    const uint32_t bB0  = sbase + OFF_B   + (bRow * BP + bCol) * 2;

    const int qr = lane >> 2;
    const int qc = (lane & 3) << 1;

    float dacc[2][8][4];
    float yacc[2][2] = {{0.f, 0.f}, {0.f, 0.f}};

    for (int d = 0; d < 4; d++) {
        const int tau = t - DLY + d;

        #pragma unroll
        for (int mt = 0; mt < 2; mt++)
            #pragma unroll
            for (int n = 0; n < 8; n++)
                #pragma unroll
                for (int q = 0; q < 4; q++) dacc[mt][n][q] = 0.0f;

        if (d > 0) {
            #pragma unroll
            for (int kt = 0; kt < 4; kt++) {
                uint32_t ahi[2][4], alo[2][4];
                #pragma unroll
                for (int mt = 0; mt < 2; mt++) {
                    const uint32_t moff = (mt * 16 * HP + kt * 16) * 2;
                    ldsm_x4(ahi[mt][0], ahi[mt][1], ahi[mt][2], ahi[mt][3], aHi0 + moff);
                    ldsm_x4(alo[mt][0], alo[mt][1], alo[mt][2], alo[mt][3], aLo0 + moff);
                }
                #pragma unroll
                for (int n = 0; n < 8; n++) {
                    uint32_t bh0, bh1, bl0, bl1;
                    ldsm_x2(bh0, bh1, bB0 + (n * 8 * BP + kt * 16) * 2);
                    ldsm_x2(bl0, bl1, bB0 + (n * 8 * BP + 64 + kt * 16) * 2);
                    #pragma unroll
                    for (int mt = 0; mt < 2; mt++) {
                        mma_bf16(dacc[mt][n], ahi[mt], bh0, bh1);
                        mma_bf16(dacc[mt][n], ahi[mt], bl0, bl1);
                        mma_bf16(dacc[mt][n], alo[mt], bh0, bh1);
                    }
                }
            }
        }

        __syncwarp();

        #pragma unroll
        for (int mt = 0; mt < 2; mt++) {
            const int r0 = m0w + mt * 16 + qr;
            #pragma unroll
            for (int n = 0; n < 8; n++) {
                const int c0 = (n << 3) + qc;
                const size_t zb = (((size_t)tau << 6) + c0) << 11;
                const float z00 = Zf[zb + g0 + r0];
                const float z01 = Zf[zb + 2048 + g0 + r0];
                const float z10 = Zf[zb + g0 + r0 + 8];
                const float z11 = Zf[zb + 2048 + g0 + r0 + 8];

                const float h00 = tanh_fast(dacc[mt][n][0] + z00);
                const float h01 = tanh_fast(dacc[mt][n][1] + z01);
                const float h10 = tanh_fast(dacc[mt][n][2] + z10);
                const float h11 = tanh_fast(dacc[mt][n][3] + z11);

                if (d < 3) {
                    const uint32_t p0 = bfpack(h00, h01);
                    const uint32_t p1 = bfpack(h10, h11);
                    const float f00 = __uint_as_float(p0 << 16);
                    const float f01 = __uint_as_float(p0 & 0xFFFF0000u);
                    const float f10 = __uint_as_float(p1 << 16);
                    const float f11 = __uint_as_float(p1 & 0xFFFF0000u);
                    const uint32_t q0 = bfpack(h00 - f00, h01 - f01);
                    const uint32_t q1 = bfpack(h10 - f10, h11 - f11);
                    const int o0 = (r0 * HP + c0) * 2;
                    const int o1 = ((r0 + 8) * HP + c0) * 2;
                    *(uint32_t*)(sm + o0)           = p0;
                    *(uint32_t*)(sm + o1)           = p1;
                    *(uint32_t*)(sm + OFF_HLO + o0) = q0;
                    *(uint32_t*)(sm + OFF_HLO + o1) = q1;
                } else {
                    const float w0 = sWo[c0], w1 = sWo[c0 + 1];
                    yacc[mt][0] += h00 * w0 + h01 * w1;
                    yacc[mt][1] += h10 * w0 + h11 * w1;
                }
            }
        }
        __syncwarp();
    }

    const float bo = sBo[0];
    #pragma unroll
    for (int mt = 0; mt < 2; mt++)
        #pragma unroll
        for (int hf = 0; hf < 2; hf++) {
            float v = yacc[mt][hf];
            v += __shfl_xor_sync(0xFFFFFFFFu, v, 1);
            v += __shfl_xor_sync(0xFFFFFFFFu, v, 2);
            if ((lane & 3) == 0) {
                const int row = m0w + mt * 16 + qr + hf * 8;
                out[(size_t)t * NG + g0 + row] = v + bo;
            }
        }
}

extern "C" void kernel_launch(void* const* d_in, const int* in_sizes, int n_in,
                              void* d_out, int out_size) {
    const float* x     = (const float*)d_in[0];
    const float* W_in  = (const float*)d_in[1];
    const float* b_in  = (const float*)d_in[2];
    const float* W_xh  = (const float*)d_in[3];
    const float* W_hh  = (const float*)d_in[4];
    const float* b_h   = (const float*)d_in[5];
    const float* W_out = (const float*)d_in[6];
    const float* b_out = (const float*)d_in[7];
    float* out = (float*)d_out;

    cudaFuncSetAttribute(uz_tc, cudaFuncAttributeMaxDynamicSharedMemorySize,
                         UZ_SMEM);
    cudaFuncSetAttribute(narx_tc, cudaFuncAttributeMaxDynamicSharedMemorySize,
                         TC_SMEM);

    uz_tc<<<NT * 16, 128, UZ_SMEM>>>(x, W_in, b_in, W_xh, b_h, out);
    narx_tc<<<(NT - DLY) * 16, 128, TC_SMEM>>>(W_hh, W_out, b_out, out);
    (void)in_sizes; (void)n_in; (void)out_size;
}